// round 13
// baseline (speedup 1.0000x reference)
#include <cuda_runtime.h>

// Fixed problem shapes
#define BSZ  4
#define TT   1024
#define DDIM 512
#define HH   8
#define DH   64
#define MROWS (BSZ*TT)   // 4096
#define NBH   (BSZ*HH)   // 32
#define INV_TAU 10.0f

typedef unsigned long long u64;

// ---- packed f32x2 helpers (k_qkv / k_score only — fma-issue-bound MACs) ----
__device__ __forceinline__ u64 pk2(float lo, float hi) {
    u64 o;
    asm("mov.b64 %0, {%1, %2};" : "=l"(o)
        : "r"(__float_as_uint(lo)), "r"(__float_as_uint(hi)));
    return o;
}
__device__ __forceinline__ u64 bcast2(float v) { return pk2(v, v); }
__device__ __forceinline__ void fma2(u64& d, u64 a, u64 b) {
    asm("fma.rn.f32x2 %0, %1, %2, %3;" : "=l"(d) : "l"(a), "l"(b), "l"(d));
}
__device__ __forceinline__ void upk2(u64 v, float& lo, float& hi) {
    unsigned int x, y;
    asm("mov.b64 {%0, %1}, %2;" : "=r"(x), "=r"(y) : "l"(v));
    lo = __uint_as_float(x); hi = __uint_as_float(y);
}

// Scratch (device globals: allocation-free)
__device__ __align__(128) float g_qkv[3][MROWS][DDIM];   // 25 MB: q,k,v post-softmax
__device__ __align__(128) float g_S[NBH][TT][TT];        // 134 MB: scores -> scan
__device__ __align__(128) int   g_rowmax[NBH][TT];       // per-row max of scan out (>=0)

// ---------------------------------------------------------------------------
// K1: QKV projections + fused per-head softmax(x/tau) epilogue.
// 128x128 tile, BK=16, A/B double-buffered smem, 8x8/thread via FFMA2 pairs.
// grid (4, 32, 3), block 256.
// ---------------------------------------------------------------------------
__global__ __launch_bounds__(256) void k_qkv(const float* __restrict__ X,
                                             const float* __restrict__ Wq,
                                             const float* __restrict__ Wk,
                                             const float* __restrict__ Wv) {
    const float* W = (blockIdx.z == 0) ? Wq : ((blockIdx.z == 1) ? Wk : Wv);
    float* Out = &g_qkv[blockIdx.z][0][0];
    __shared__ float As[2][16][128];
    __shared__ float Bs[2][16][128];
    int tid = threadIdx.x;
    int m0 = blockIdx.y * 128, n0 = blockIdx.x * 128;
    int ar = tid >> 1, ac = (tid & 1) * 8;
    int br = tid >> 4, bc = (tid & 15) * 8;
    int tx = tid & 15, ty = tid >> 4;
    u64 acc2[8][4];
#pragma unroll
    for (int r = 0; r < 8; r++)
#pragma unroll
        for (int j = 0; j < 4; j++) acc2[r][j] = 0ull;

    float4 a0 = *(const float4*)&X[(m0 + ar) * DDIM + ac];
    float4 a1 = *(const float4*)&X[(m0 + ar) * DDIM + ac + 4];
    float4 b0 = *(const float4*)&W[br * DDIM + n0 + bc];
    float4 b1 = *(const float4*)&W[br * DDIM + n0 + bc + 4];
    As[0][ac + 0][ar] = a0.x; As[0][ac + 1][ar] = a0.y;
    As[0][ac + 2][ar] = a0.z; As[0][ac + 3][ar] = a0.w;
    As[0][ac + 4][ar] = a1.x; As[0][ac + 5][ar] = a1.y;
    As[0][ac + 6][ar] = a1.z; As[0][ac + 7][ar] = a1.w;
    *(float4*)&Bs[0][br][bc]     = b0;
    *(float4*)&Bs[0][br][bc + 4] = b1;
    __syncthreads();

    int cur = 0;
    for (int k0 = 0; k0 < DDIM; k0 += 16) {
        int nk = k0 + 16;
        if (nk < DDIM) {
            a0 = *(const float4*)&X[(m0 + ar) * DDIM + nk + ac];
            a1 = *(const float4*)&X[(m0 + ar) * DDIM + nk + ac + 4];
            b0 = *(const float4*)&W[(nk + br) * DDIM + n0 + bc];
            b1 = *(const float4*)&W[(nk + br) * DDIM + n0 + bc + 4];
        }
#pragma unroll
        for (int k = 0; k < 16; k++) {
            float a[8], bb[8];
            *(float4*)&a[0]  = *(const float4*)&As[cur][k][ty * 8];
            *(float4*)&a[4]  = *(const float4*)&As[cur][k][ty * 8 + 4];
            *(float4*)&bb[0] = *(const float4*)&Bs[cur][k][tx * 8];
            *(float4*)&bb[4] = *(const float4*)&Bs[cur][k][tx * 8 + 4];
            u64 bp[4];
            bp[0] = pk2(bb[0], bb[1]); bp[1] = pk2(bb[2], bb[3]);
            bp[2] = pk2(bb[4], bb[5]); bp[3] = pk2(bb[6], bb[7]);
#pragma unroll
            for (int r = 0; r < 8; r++) {
                u64 ap = bcast2(a[r]);
#pragma unroll
                for (int j = 0; j < 4; j++) fma2(acc2[r][j], ap, bp[j]);
            }
        }
        if (nk < DDIM) {
            int nxt = cur ^ 1;
            As[nxt][ac + 0][ar] = a0.x; As[nxt][ac + 1][ar] = a0.y;
            As[nxt][ac + 2][ar] = a0.z; As[nxt][ac + 3][ar] = a0.w;
            As[nxt][ac + 4][ar] = a1.x; As[nxt][ac + 5][ar] = a1.y;
            As[nxt][ac + 6][ar] = a1.z; As[nxt][ac + 7][ar] = a1.w;
            *(float4*)&Bs[nxt][br][bc]     = b0;
            *(float4*)&Bs[nxt][br][bc + 4] = b1;
            __syncthreads();
            cur = nxt;
        }
    }

    float acc[8][8];
#pragma unroll
    for (int r = 0; r < 8; r++)
#pragma unroll
        for (int j = 0; j < 4; j++) upk2(acc2[r][j], acc[r][2 * j], acc[r][2 * j + 1]);

#pragma unroll
    for (int r = 0; r < 8; r++) {
        float mx = acc[r][0];
#pragma unroll
        for (int c = 1; c < 8; c++) mx = fmaxf(mx, acc[r][c]);
#pragma unroll
        for (int o = 4; o > 0; o >>= 1) mx = fmaxf(mx, __shfl_xor_sync(0xffffffffu, mx, o));
        float s = 0.f;
#pragma unroll
        for (int c = 0; c < 8; c++) {
            acc[r][c] = __expf((acc[r][c] - mx) * INV_TAU);
            s += acc[r][c];
        }
#pragma unroll
        for (int o = 4; o > 0; o >>= 1) s += __shfl_xor_sync(0xffffffffu, s, o);
        float inv = 1.f / s;
#pragma unroll
        for (int c = 0; c < 8; c++) acc[r][c] *= inv;
    }
#pragma unroll
    for (int r = 0; r < 8; r++) {
        int row = m0 + ty * 8 + r;
        *(float4*)&Out[row * DDIM + n0 + tx * 8]     = *(float4*)&acc[r][0];
        *(float4*)&Out[row * DDIM + n0 + tx * 8 + 4] = *(float4*)&acc[r][4];
    }
}

// ---------------------------------------------------------------------------
// K3: S = q_sm·k_smT, causal 128x128 tiles, BK=32, 8x8/thread via FFMA2.
// Diagonal blocks (jt==it) also zero g_rowmax for their 128 rows (kernel
// boundary orders this before k_scan's REDs). grid (8, 8, 32), block 256.
// ---------------------------------------------------------------------------
__global__ __launch_bounds__(256) void k_score() {
    int jt = blockIdx.x, it = blockIdx.y, bh = blockIdx.z;
    if (jt > it) return;
    int b = bh >> 3, h = bh & 7;
    if (jt == it && threadIdx.x < 128)
        g_rowmax[bh][it * 128 + threadIdx.x] = 0;
    const float* Q  = &g_qkv[0][b * TT][h * DH];
    const float* Kp = &g_qkv[1][b * TT][h * DH];
    __shared__ float Qs[32][132];
    __shared__ float Ks[32][132];
    int tid = threadIdx.x;
    int tx = tid & 15, ty = tid >> 4;
    u64 acc2[8][4];
#pragma unroll
    for (int r = 0; r < 8; r++)
#pragma unroll
        for (int j = 0; j < 4; j++) acc2[r][j] = 0ull;

    for (int k0 = 0; k0 < DH; k0 += 32) {
        __syncthreads();
#pragma unroll
        for (int l = 0; l < 4; l++) {
            int idx = tid + l * 256;
            int row = idx >> 3, cg = (idx & 7) * 4;
            float4 q4 = *(const float4*)&Q[(it * 128 + row) * DDIM + k0 + cg];
            float4 k4 = *(const float4*)&Kp[(jt * 128 + row) * DDIM + k0 + cg];
            Qs[cg + 0][row] = q4.x; Qs[cg + 1][row] = q4.y;
            Qs[cg + 2][row] = q4.z; Qs[cg + 3][row] = q4.w;
            Ks[cg + 0][row] = k4.x; Ks[cg + 1][row] = k4.y;
            Ks[cg + 2][row] = k4.z; Ks[cg + 3][row] = k4.w;
        }
        __syncthreads();
#pragma unroll
        for (int k = 0; k < 32; k++) {
            float a[8], bb[8];
            *(float4*)&a[0]  = *(const float4*)&Qs[k][ty * 8];
            *(float4*)&a[4]  = *(const float4*)&Qs[k][ty * 8 + 4];
            *(float4*)&bb[0] = *(const float4*)&Ks[k][tx * 8];
            *(float4*)&bb[4] = *(const float4*)&Ks[k][tx * 8 + 4];
            u64 bp[4];
            bp[0] = pk2(bb[0], bb[1]); bp[1] = pk2(bb[2], bb[3]);
            bp[2] = pk2(bb[4], bb[5]); bp[3] = pk2(bb[6], bb[7]);
#pragma unroll
            for (int r = 0; r < 8; r++) {
                u64 ap = bcast2(a[r]);
#pragma unroll
                for (int j = 0; j < 4; j++) fma2(acc2[r][j], ap, bp[j]);
            }
        }
    }
    float* Sp = &g_S[bh][0][0];
#pragma unroll
    for (int r = 0; r < 8; r++) {
        float acc[8];
#pragma unroll
        for (int j = 0; j < 4; j++) upk2(acc2[r][j], acc[2 * j], acc[2 * j + 1]);
        int row = it * 128 + ty * 8 + r;
        *(float4*)&Sp[row * TT + jt * 128 + tx * 8]     = *(float4*)&acc[0];
        *(float4*)&Sp[row * TT + jt * 128 + tx * 8 + 4] = *(float4*)&acc[4];
    }
}

// ---------------------------------------------------------------------------
// K4: per-subdiagonal scan, in place on g_S, now ALSO publishing per-row max
// of the (>=0) scan outputs via fire-and-forget atomicMax (REDG.MAX, no
// warp stall; float-as-int ordering valid for non-negative floats).
// A/B double-buffered 32-row blocks, 1D longest-first grid. grid 256, blk 128.
// ---------------------------------------------------------------------------
#define SPF 32
__global__ __launch_bounds__(128) void k_scan() {
    int bid = blockIdx.x;
    int bh = bid & 31;
    int dbase = (bid >> 5) * 128;
    int d = dbase + threadIdx.x;
    float* Sp = &g_S[bh][0][0];
    int* Rm = &g_rowmax[bh][0];
    float bufA[SPF], bufB[SPF];
    float s = 0.f, m = 0.f;
#pragma unroll
    for (int p = 0; p < SPF; p++) {
        int i = dbase + p, j = i - d;
        bufA[p] = (j >= 0) ? Sp[i * TT + j] : 0.f;
    }
    for (int ib = dbase; ib < TT; ib += 2 * SPF) {
#pragma unroll
        for (int p = 0; p < SPF; p++) {
            int i = ib + SPF + p, j = i - d;
            bufB[p] = (i < TT && j >= 0) ? Sp[i * TT + j] : 0.f;
        }
#pragma unroll
        for (int p = 0; p < SPF; p++) {
            int i = ib + p;
            if (i >= d && i < TT) {
                float a = bufA[p];
                s += a;
                m = fmaxf(m, s * (1.f - a));
                float o = s - m;
                Sp[i * TT + (i - d)] = o;
                atomicMax(&Rm[i], __float_as_int(fmaxf(o, 0.f)));
            }
        }
#pragma unroll
        for (int p = 0; p < SPF; p++) {
            int i = ib + 2 * SPF + p, j = i - d;
            bufA[p] = (i < TT && j >= 0) ? Sp[i * TT + j] : 0.f;
        }
#pragma unroll
        for (int p = 0; p < SPF; p++) {
            int i = ib + SPF + p;
            if (i >= d && i < TT) {
                float a = bufB[p];
                s += a;
                m = fmaxf(m, s * (1.f - a));
                float o = s - m;
                Sp[i * TT + (i - d)] = o;
                atomicMax(&Rm[i], __float_as_int(fmaxf(o, 0.f)));
            }
        }
    }
}

// ---------------------------------------------------------------------------
// K5: fused causal softmax((scan + j/(i+1))/tau) + P@V + output projection.
// SHIFT-BASED softmax: shift = rowmax + 1 >= every logit of the row
// (pos < 1), known before the loop -> NO per-tile shuffles, NO max tracking,
// NO accumulator rescaling. ssum per-thread, reduced once at the end
// (softmax is exactly shift-invariant). grid 512 (heavy-first), block 256.
// ---------------------------------------------------------------------------
__global__ __launch_bounds__(256, 4) void k_pvsm(const float* __restrict__ wo,
                                                 float* __restrict__ out) {
    int bid = blockIdx.x;
    int it = 15 - (bid >> 5);
    int bh = bid & 31;
    int b = bh >> 3, h = bh & 7;
    const float* Sp = &g_S[bh][0][0];
    const float* V = &g_qkv[2][b * TT][h * DH];
    __shared__ float Vs[64][68];   // V tile [j][d] (reused for wo in epilogue)
    __shared__ float Ps[64][68];   // logits -> probs [row][j] (reused for O)
    int tid = threadIdx.x;
    int tx = tid & 15, ty = tid >> 4;
    int i0 = it * 64;

    float acc[4][4], ssum[4], invi[4], shift[4];
    int gi[4];
#pragma unroll
    for (int r = 0; r < 4; r++) {
        gi[r] = i0 + ty * 4 + r;
        invi[r] = 1.f / (float)(gi[r] + 1);
        shift[r] = __int_as_float(g_rowmax[bh][gi[r]]) + 1.0f;
        ssum[r] = 0.f;
#pragma unroll
        for (int c = 0; c < 4; c++) acc[r][c] = 0.f;
    }

    for (int jt = 0; jt <= it; jt++) {
        int j0 = jt * 64;
#pragma unroll
        for (int l = 0; l < 4; l++) {
            int row = ty + l * 16;
            *(float4*)&Ps[row][tx * 4] = *(const float4*)&Sp[(i0 + row) * TT + j0 + tx * 4];
            *(float4*)&Vs[row][tx * 4] = *(const float4*)&V[(j0 + row) * DDIM + tx * 4];
        }
        __syncthreads();

        // in-place shift-softmax: logits -> probs, zero shuffles
#pragma unroll
        for (int r = 0; r < 4; r++) {
            float4 s4 = *(float4*)&Ps[ty * 4 + r][tx * 4];
            int jb = j0 + tx * 4;
            float p0 = (jb + 0 <= gi[r]) ? __expf((s4.x + (float)(jb + 0) * invi[r] - shift[r]) * INV_TAU) : 0.f;
            float p1 = (jb + 1 <= gi[r]) ? __expf((s4.y + (float)(jb + 1) * invi[r] - shift[r]) * INV_TAU) : 0.f;
            float p2 = (jb + 2 <= gi[r]) ? __expf((s4.z + (float)(jb + 2) * invi[r] - shift[r]) * INV_TAU) : 0.f;
            float p3 = (jb + 3 <= gi[r]) ? __expf((s4.w + (float)(jb + 3) * invi[r] - shift[r]) * INV_TAU) : 0.f;
            ssum[r] += p0 + p1 + p2 + p3;
            float4 p4 = {p0, p1, p2, p3};
            *(float4*)&Ps[ty * 4 + r][tx * 4] = p4;
        }
        __syncthreads();

#pragma unroll 8
        for (int k4 = 0; k4 < 64; k4 += 4) {
            float4 a0 = *(float4*)&Ps[ty * 4 + 0][k4];
            float4 a1 = *(float4*)&Ps[ty * 4 + 1][k4];
            float4 a2 = *(float4*)&Ps[ty * 4 + 2][k4];
            float4 a3 = *(float4*)&Ps[ty * 4 + 3][k4];
            float4 b0 = *(float4*)&Vs[k4 + 0][tx * 4];
            float4 b1 = *(float4*)&Vs[k4 + 1][tx * 4];
            float4 b2 = *(float4*)&Vs[k4 + 2][tx * 4];
            float4 b3 = *(float4*)&Vs[k4 + 3][tx * 4];
            float ar[4][4] = {{a0.x, a0.y, a0.z, a0.w},
                              {a1.x, a1.y, a1.z, a1.w},
                              {a2.x, a2.y, a2.z, a2.w},
                              {a3.x, a3.y, a3.z, a3.w}};
            float bb[4][4] = {{b0.x, b0.y, b0.z, b0.w},
                              {b1.x, b1.y, b1.z, b1.w},
                              {b2.x, b2.y, b2.z, b2.w},
                              {b3.x, b3.y, b3.z, b3.w}};
#pragma unroll
            for (int r = 0; r < 4; r++)
#pragma unroll
                for (int kk = 0; kk < 4; kk++)
#pragma unroll
                    for (int c = 0; c < 4; c++)
                        acc[r][c] += ar[r][kk] * bb[kk][c];
        }
        __syncthreads();
    }

    // one reduction of ssum over the 16-lane row group
#pragma unroll
    for (int r = 0; r < 4; r++) {
#pragma unroll
        for (int o = 8; o > 0; o >>= 1)
            ssum[r] += __shfl_xor_sync(0xffffffffu, ssum[r], o);
    }

    // ---- fused output projection: out = O(64xDh) @ wo_h(64x64) ----
#pragma unroll
    for (int r = 0; r < 4; r++) {
        float inv = 1.f / ssum[r];
        float4 o4 = {acc[r][0] * inv, acc[r][1] * inv, acc[r][2] * inv, acc[r][3] * inv};
        *(float4*)&Ps[ty * 4 + r][tx * 4] = o4;
    }
#pragma unroll
    for (int l = 0; l < 4; l++) {
        int row = ty + l * 16;
        *(float4*)&Vs[row][tx * 4] = *(const float4*)&wo[(h * 64 + row) * 64 + tx * 4];
    }
    __syncthreads();

    float acc2[4][4];
#pragma unroll
    for (int r = 0; r < 4; r++)
#pragma unroll
        for (int c = 0; c < 4; c++) acc2[r][c] = 0.f;
#pragma unroll 8
    for (int k4 = 0; k4 < 64; k4 += 4) {
        float4 b0 = *(float4*)&Vs[k4 + 0][tx * 4];
        float4 b1 = *(float4*)&Vs[k4 + 1][tx * 4];
        float4 b2 = *(float4*)&Vs[k4 + 2][tx * 4];
        float4 b3 = *(float4*)&Vs[k4 + 3][tx * 4];
#pragma unroll
        for (int r = 0; r < 4; r++) {
            float4 a = *(float4*)&Ps[ty * 4 + r][k4];
            acc2[r][0] += a.x * b0.x + a.y * b1.x + a.z * b2.x + a.w * b3.x;
            acc2[r][1] += a.x * b0.y + a.y * b1.y + a.z * b2.y + a.w * b3.y;
            acc2[r][2] += a.x * b0.z + a.y * b1.z + a.z * b2.z + a.w * b3.z;
            acc2[r][3] += a.x * b0.w + a.y * b1.w + a.z * b2.w + a.w * b3.w;
        }
    }
#pragma unroll
    for (int r = 0; r < 4; r++) {
        int t = i0 + ty * 4 + r;
        float4 o4 = {acc2[r][0], acc2[r][1], acc2[r][2], acc2[r][3]};
        *(float4*)&out[(b * TT + t) * DDIM + h * 64 + tx * 4] = o4;
    }
}

// ---------------------------------------------------------------------------
extern "C" void kernel_launch(void* const* d_in, const int* in_sizes, int n_in,
                              void* d_out, int out_size) {
    const float* x  = (const float*)d_in[0];
    const float* wq = (const float*)d_in[1];
    const float* wk = (const float*)d_in[2];
    const float* wv = (const float*)d_in[3];
    const float* wo = (const float*)d_in[4];
    float* out = (float*)d_out;

    k_qkv<<<dim3(4, 32, 3), 256>>>(x, wq, wk, wv);
    k_score<<<dim3(8, 8, 32), 256>>>();
    k_scan<<<256, 128>>>();
    k_pvsm<<<512, 256>>>(wo, out);
}

// round 14
// speedup vs baseline: 1.0883x; 1.0883x over previous
#include <cuda_runtime.h>

// Fixed problem shapes
#define BSZ  4
#define TT   1024
#define DDIM 512
#define HH   8
#define DH   64
#define MROWS (BSZ*TT)   // 4096
#define NBH   (BSZ*HH)   // 32
#define INV_TAU 10.0f

typedef unsigned long long u64;

// ---- packed f32x2 helpers (k_qkv / k_score only — fma-issue-bound MACs) ----
__device__ __forceinline__ u64 pk2(float lo, float hi) {
    u64 o;
    asm("mov.b64 %0, {%1, %2};" : "=l"(o)
        : "r"(__float_as_uint(lo)), "r"(__float_as_uint(hi)));
    return o;
}
__device__ __forceinline__ u64 bcast2(float v) { return pk2(v, v); }
__device__ __forceinline__ void fma2(u64& d, u64 a, u64 b) {
    asm("fma.rn.f32x2 %0, %1, %2, %3;" : "=l"(d) : "l"(a), "l"(b), "l"(d));
}
__device__ __forceinline__ void upk2(u64 v, float& lo, float& hi) {
    unsigned int x, y;
    asm("mov.b64 {%0, %1}, %2;" : "=r"(x), "=r"(y) : "l"(v));
    lo = __uint_as_float(x); hi = __uint_as_float(y);
}

// ---- cp.async helpers ----
__device__ __forceinline__ void cpa16(unsigned int dst_smem, const void* src) {
    asm volatile("cp.async.cg.shared.global [%0], [%1], 16;"
                 :: "r"(dst_smem), "l"(src));
}
__device__ __forceinline__ void cpa_commit() {
    asm volatile("cp.async.commit_group;");
}
__device__ __forceinline__ void cpa_wait0() {
    asm volatile("cp.async.wait_group 0;");
}

// Scratch (device globals: allocation-free)
__device__ __align__(128) float g_qkv[3][MROWS][DDIM];   // 25 MB: q,k,v post-softmax
__device__ __align__(128) float g_S[NBH][TT][TT];        // 134 MB: scores -> scan

// ---------------------------------------------------------------------------
// K1: QKV projections + fused per-head softmax(x/tau) epilogue.
// 128x128 tile, BK=16, A/B double-buffered smem, 8x8/thread via FFMA2 pairs.
// grid (4, 32, 3), block 256.
// ---------------------------------------------------------------------------
__global__ __launch_bounds__(256) void k_qkv(const float* __restrict__ X,
                                             const float* __restrict__ Wq,
                                             const float* __restrict__ Wk,
                                             const float* __restrict__ Wv) {
    const float* W = (blockIdx.z == 0) ? Wq : ((blockIdx.z == 1) ? Wk : Wv);
    float* Out = &g_qkv[blockIdx.z][0][0];
    __shared__ float As[2][16][128];
    __shared__ float Bs[2][16][128];
    int tid = threadIdx.x;
    int m0 = blockIdx.y * 128, n0 = blockIdx.x * 128;
    int ar = tid >> 1, ac = (tid & 1) * 8;
    int br = tid >> 4, bc = (tid & 15) * 8;
    int tx = tid & 15, ty = tid >> 4;
    u64 acc2[8][4];
#pragma unroll
    for (int r = 0; r < 8; r++)
#pragma unroll
        for (int j = 0; j < 4; j++) acc2[r][j] = 0ull;

    float4 a0 = *(const float4*)&X[(m0 + ar) * DDIM + ac];
    float4 a1 = *(const float4*)&X[(m0 + ar) * DDIM + ac + 4];
    float4 b0 = *(const float4*)&W[br * DDIM + n0 + bc];
    float4 b1 = *(const float4*)&W[br * DDIM + n0 + bc + 4];
    As[0][ac + 0][ar] = a0.x; As[0][ac + 1][ar] = a0.y;
    As[0][ac + 2][ar] = a0.z; As[0][ac + 3][ar] = a0.w;
    As[0][ac + 4][ar] = a1.x; As[0][ac + 5][ar] = a1.y;
    As[0][ac + 6][ar] = a1.z; As[0][ac + 7][ar] = a1.w;
    *(float4*)&Bs[0][br][bc]     = b0;
    *(float4*)&Bs[0][br][bc + 4] = b1;
    __syncthreads();

    int cur = 0;
    for (int k0 = 0; k0 < DDIM; k0 += 16) {
        int nk = k0 + 16;
        if (nk < DDIM) {
            a0 = *(const float4*)&X[(m0 + ar) * DDIM + nk + ac];
            a1 = *(const float4*)&X[(m0 + ar) * DDIM + nk + ac + 4];
            b0 = *(const float4*)&W[(nk + br) * DDIM + n0 + bc];
            b1 = *(const float4*)&W[(nk + br) * DDIM + n0 + bc + 4];
        }
#pragma unroll
        for (int k = 0; k < 16; k++) {
            float a[8], bb[8];
            *(float4*)&a[0]  = *(const float4*)&As[cur][k][ty * 8];
            *(float4*)&a[4]  = *(const float4*)&As[cur][k][ty * 8 + 4];
            *(float4*)&bb[0] = *(const float4*)&Bs[cur][k][tx * 8];
            *(float4*)&bb[4] = *(const float4*)&Bs[cur][k][tx * 8 + 4];
            u64 bp[4];
            bp[0] = pk2(bb[0], bb[1]); bp[1] = pk2(bb[2], bb[3]);
            bp[2] = pk2(bb[4], bb[5]); bp[3] = pk2(bb[6], bb[7]);
#pragma unroll
            for (int r = 0; r < 8; r++) {
                u64 ap = bcast2(a[r]);
#pragma unroll
                for (int j = 0; j < 4; j++) fma2(acc2[r][j], ap, bp[j]);
            }
        }
        if (nk < DDIM) {
            int nxt = cur ^ 1;
            As[nxt][ac + 0][ar] = a0.x; As[nxt][ac + 1][ar] = a0.y;
            As[nxt][ac + 2][ar] = a0.z; As[nxt][ac + 3][ar] = a0.w;
            As[nxt][ac + 4][ar] = a1.x; As[nxt][ac + 5][ar] = a1.y;
            As[nxt][ac + 6][ar] = a1.z; As[nxt][ac + 7][ar] = a1.w;
            *(float4*)&Bs[nxt][br][bc]     = b0;
            *(float4*)&Bs[nxt][br][bc + 4] = b1;
            __syncthreads();
            cur = nxt;
        }
    }

    float acc[8][8];
#pragma unroll
    for (int r = 0; r < 8; r++)
#pragma unroll
        for (int j = 0; j < 4; j++) upk2(acc2[r][j], acc[r][2 * j], acc[r][2 * j + 1]);

#pragma unroll
    for (int r = 0; r < 8; r++) {
        float mx = acc[r][0];
#pragma unroll
        for (int c = 1; c < 8; c++) mx = fmaxf(mx, acc[r][c]);
#pragma unroll
        for (int o = 4; o > 0; o >>= 1) mx = fmaxf(mx, __shfl_xor_sync(0xffffffffu, mx, o));
        float s = 0.f;
#pragma unroll
        for (int c = 0; c < 8; c++) {
            acc[r][c] = __expf((acc[r][c] - mx) * INV_TAU);
            s += acc[r][c];
        }
#pragma unroll
        for (int o = 4; o > 0; o >>= 1) s += __shfl_xor_sync(0xffffffffu, s, o);
        float inv = 1.f / s;
#pragma unroll
        for (int c = 0; c < 8; c++) acc[r][c] *= inv;
    }
#pragma unroll
    for (int r = 0; r < 8; r++) {
        int row = m0 + ty * 8 + r;
        *(float4*)&Out[row * DDIM + n0 + tx * 8]     = *(float4*)&acc[r][0];
        *(float4*)&Out[row * DDIM + n0 + tx * 8 + 4] = *(float4*)&acc[r][4];
    }
}

// ---------------------------------------------------------------------------
// K3: S = q_sm·k_smT, causal 128x128 tiles, BK=32, 8x8/thread via FFMA2.
// grid (8, 8, 32), block 256.
// ---------------------------------------------------------------------------
__global__ __launch_bounds__(256) void k_score() {
    int jt = blockIdx.x, it = blockIdx.y, bh = blockIdx.z;
    if (jt > it) return;
    int b = bh >> 3, h = bh & 7;
    const float* Q  = &g_qkv[0][b * TT][h * DH];
    const float* Kp = &g_qkv[1][b * TT][h * DH];
    __shared__ float Qs[32][132];
    __shared__ float Ks[32][132];
    int tid = threadIdx.x;
    int tx = tid & 15, ty = tid >> 4;
    u64 acc2[8][4];
#pragma unroll
    for (int r = 0; r < 8; r++)
#pragma unroll
        for (int j = 0; j < 4; j++) acc2[r][j] = 0ull;

    for (int k0 = 0; k0 < DH; k0 += 32) {
        __syncthreads();
#pragma unroll
        for (int l = 0; l < 4; l++) {
            int idx = tid + l * 256;
            int row = idx >> 3, cg = (idx & 7) * 4;
            float4 q4 = *(const float4*)&Q[(it * 128 + row) * DDIM + k0 + cg];
            float4 k4 = *(const float4*)&Kp[(jt * 128 + row) * DDIM + k0 + cg];
            Qs[cg + 0][row] = q4.x; Qs[cg + 1][row] = q4.y;
            Qs[cg + 2][row] = q4.z; Qs[cg + 3][row] = q4.w;
            Ks[cg + 0][row] = k4.x; Ks[cg + 1][row] = k4.y;
            Ks[cg + 2][row] = k4.z; Ks[cg + 3][row] = k4.w;
        }
        __syncthreads();
#pragma unroll
        for (int k = 0; k < 32; k++) {
            float a[8], bb[8];
            *(float4*)&a[0]  = *(const float4*)&Qs[k][ty * 8];
            *(float4*)&a[4]  = *(const float4*)&Qs[k][ty * 8 + 4];
            *(float4*)&bb[0] = *(const float4*)&Ks[k][tx * 8];
            *(float4*)&bb[4] = *(const float4*)&Ks[k][tx * 8 + 4];
            u64 bp[4];
            bp[0] = pk2(bb[0], bb[1]); bp[1] = pk2(bb[2], bb[3]);
            bp[2] = pk2(bb[4], bb[5]); bp[3] = pk2(bb[6], bb[7]);
#pragma unroll
            for (int r = 0; r < 8; r++) {
                u64 ap = bcast2(a[r]);
#pragma unroll
                for (int j = 0; j < 4; j++) fma2(acc2[r][j], ap, bp[j]);
            }
        }
    }
    float* Sp = &g_S[bh][0][0];
#pragma unroll
    for (int r = 0; r < 8; r++) {
        float acc[8];
#pragma unroll
        for (int j = 0; j < 4; j++) upk2(acc2[r][j], acc[2 * j], acc[2 * j + 1]);
        int row = it * 128 + ty * 8 + r;
        *(float4*)&Sp[row * TT + jt * 128 + tx * 8]     = *(float4*)&acc[0];
        *(float4*)&Sp[row * TT + jt * 128 + tx * 8 + 4] = *(float4*)&acc[4];
    }
}

// ---------------------------------------------------------------------------
// K4: per-subdiagonal scan, in place on g_S. A/B double-buffered 32-row
// blocks. 1D grid, longest blocks first. grid 256, block 128.
// ---------------------------------------------------------------------------
#define SPF 32
__global__ __launch_bounds__(128) void k_scan() {
    int bid = blockIdx.x;
    int bh = bid & 31;
    int dbase = (bid >> 5) * 128;
    int d = dbase + threadIdx.x;
    float* Sp = &g_S[bh][0][0];
    float bufA[SPF], bufB[SPF];
    float s = 0.f, m = 0.f;
#pragma unroll
    for (int p = 0; p < SPF; p++) {
        int i = dbase + p, j = i - d;
        bufA[p] = (j >= 0) ? Sp[i * TT + j] : 0.f;
    }
    for (int ib = dbase; ib < TT; ib += 2 * SPF) {
#pragma unroll
        for (int p = 0; p < SPF; p++) {
            int i = ib + SPF + p, j = i - d;
            bufB[p] = (i < TT && j >= 0) ? Sp[i * TT + j] : 0.f;
        }
#pragma unroll
        for (int p = 0; p < SPF; p++) {
            int i = ib + p;
            if (i >= d && i < TT) {
                float a = bufA[p];
                s += a;
                m = fmaxf(m, s * (1.f - a));
                Sp[i * TT + (i - d)] = s - m;
            }
        }
#pragma unroll
        for (int p = 0; p < SPF; p++) {
            int i = ib + 2 * SPF + p, j = i - d;
            bufA[p] = (i < TT && j >= 0) ? Sp[i * TT + j] : 0.f;
        }
#pragma unroll
        for (int p = 0; p < SPF; p++) {
            int i = ib + SPF + p;
            if (i >= d && i < TT) {
                float a = bufB[p];
                s += a;
                m = fmaxf(m, s * (1.f - a));
                Sp[i * TT + (i - d)] = s - m;
            }
        }
    }
}

// ---------------------------------------------------------------------------
// K5: fused causal softmax((scan + j/(i+1))/tau) + P@V + output projection.
// cp.async DOUBLE-BUFFERED pipeline: S and V tiles stream GMEM->smem with
// ping-pong buffers; prefetch for tile n+1 issued right after tile n's
// arrival barrier, hidden under softmax+MAC of tile n. 2 syncs/tile.
// Dynamic smem 69632 B (Ps[2]+Vs[2], 64x68 each). grid 512 heavy-first.
// ---------------------------------------------------------------------------
#define TILE_F (64 * 68)
__global__ __launch_bounds__(256) void k_pvsm(const float* __restrict__ wo,
                                              float* __restrict__ out) {
    extern __shared__ float sh[];
    // layout: Ps[2] then Vs[2]
    int bid = blockIdx.x;
    int it = 15 - (bid >> 5);
    int bh = bid & 31;
    int b = bh >> 3, h = bh & 7;
    const float* __restrict__ Sp = &g_S[bh][0][0];
    const float* __restrict__ V = &g_qkv[2][b * TT][h * DH];
    int tid = threadIdx.x;
    int tx = tid & 15, ty = tid >> 4;
    int i0 = it * 64;
    unsigned int shbase = (unsigned int)__cvta_generic_to_shared(sh);

    float acc[4][4], m[4], ssum[4], invi[4];
#pragma unroll
    for (int r = 0; r < 4; r++) {
        m[r] = -1e30f; ssum[r] = 0.f;
        invi[r] = 1.f / (float)(i0 + ty * 4 + r + 1);
#pragma unroll
        for (int c = 0; c < 4; c++) acc[r][c] = 0.f;
    }

    // prologue: async-load tile 0 (S rows + V rows), 4 rows per thread each
#pragma unroll
    for (int l = 0; l < 4; l++) {
        int row = ty + l * 16;
        cpa16(shbase + (row * 68 + tx * 4) * 4,
              &Sp[(i0 + row) * TT + tx * 4]);
        cpa16(shbase + (2 * TILE_F + row * 68 + tx * 4) * 4,
              &V[row * DDIM + tx * 4]);
    }
    cpa_commit();

    for (int jt = 0; jt <= it; jt++) {
        int buf = jt & 1;
        float* Ps = sh + buf * TILE_F;
        float* Vs = sh + (2 + buf) * TILE_F;
        cpa_wait0();
        __syncthreads();

        // prefetch tile jt+1 into the other buffer (covered by softmax+MAC)
        if (jt < it) {
            int j1 = (jt + 1) * 64;
            int nb = buf ^ 1;
#pragma unroll
            for (int l = 0; l < 4; l++) {
                int row = ty + l * 16;
                cpa16(shbase + (nb * TILE_F + row * 68 + tx * 4) * 4,
                      &Sp[(i0 + row) * TT + j1 + tx * 4]);
                cpa16(shbase + ((2 + nb) * TILE_F + row * 68 + tx * 4) * 4,
                      &V[(j1 + row) * DDIM + tx * 4]);
            }
        }
        cpa_commit();

        // in-place softmax on Ps[buf] (online, per-row over 16 lanes)
        int j0 = jt * 64;
#pragma unroll
        for (int r = 0; r < 4; r++) {
            int gi = i0 + ty * 4 + r;
            float4 s4 = *(float4*)&Ps[(ty * 4 + r) * 68 + tx * 4];
            float pr[4];
            int jb = j0 + tx * 4;
            pr[0] = (jb + 0 <= gi) ? s4.x + (float)(jb + 0) * invi[r] : -1e30f;
            pr[1] = (jb + 1 <= gi) ? s4.y + (float)(jb + 1) * invi[r] : -1e30f;
            pr[2] = (jb + 2 <= gi) ? s4.z + (float)(jb + 2) * invi[r] : -1e30f;
            pr[3] = (jb + 3 <= gi) ? s4.w + (float)(jb + 3) * invi[r] : -1e30f;
            float lmx = fmaxf(fmaxf(pr[0], pr[1]), fmaxf(pr[2], pr[3]));
#pragma unroll
            for (int o = 8; o > 0; o >>= 1)
                lmx = fmaxf(lmx, __shfl_xor_sync(0xffffffffu, lmx, o));
            float nm = fmaxf(m[r], lmx);
            float scale = __expf((m[r] - nm) * INV_TAU);
            m[r] = nm;
            float ts = 0.f;
#pragma unroll
            for (int c = 0; c < 4; c++) {
                float e = __expf((pr[c] - nm) * INV_TAU);
                pr[c] = e;
                ts += e;
            }
#pragma unroll
            for (int o = 8; o > 0; o >>= 1)
                ts += __shfl_xor_sync(0xffffffffu, ts, o);
            ssum[r] = ssum[r] * scale + ts;
#pragma unroll
            for (int c = 0; c < 4; c++) acc[r][c] *= scale;
            float4 p4 = {pr[0], pr[1], pr[2], pr[3]};
            *(float4*)&Ps[(ty * 4 + r) * 68 + tx * 4] = p4;
        }
        __syncthreads();

        // MAC: acc += P @ V
#pragma unroll 8
        for (int k4 = 0; k4 < 64; k4 += 4) {
            float4 a0 = *(float4*)&Ps[(ty * 4 + 0) * 68 + k4];
            float4 a1 = *(float4*)&Ps[(ty * 4 + 1) * 68 + k4];
            float4 a2 = *(float4*)&Ps[(ty * 4 + 2) * 68 + k4];
            float4 a3 = *(float4*)&Ps[(ty * 4 + 3) * 68 + k4];
            float4 b0 = *(float4*)&Vs[(k4 + 0) * 68 + tx * 4];
            float4 b1 = *(float4*)&Vs[(k4 + 1) * 68 + tx * 4];
            float4 b2 = *(float4*)&Vs[(k4 + 2) * 68 + tx * 4];
            float4 b3 = *(float4*)&Vs[(k4 + 3) * 68 + tx * 4];
            float ar[4][4] = {{a0.x, a0.y, a0.z, a0.w},
                              {a1.x, a1.y, a1.z, a1.w},
                              {a2.x, a2.y, a2.z, a2.w},
                              {a3.x, a3.y, a3.z, a3.w}};
            float bb[4][4] = {{b0.x, b0.y, b0.z, b0.w},
                              {b1.x, b1.y, b1.z, b1.w},
                              {b2.x, b2.y, b2.z, b2.w},
                              {b3.x, b3.y, b3.z, b3.w}};
#pragma unroll
            for (int r = 0; r < 4; r++)
#pragma unroll
                for (int kk = 0; kk < 4; kk++)
#pragma unroll
                    for (int c = 0; c < 4; c++)
                        acc[r][c] += ar[r][kk] * bb[kk][c];
        }
        // no trailing sync: next write goes to the OTHER buffer and is issued
        // only after next iteration's arrival barrier.
    }
    __syncthreads();

    // ---- fused output projection: out = O(64xDh) @ wo_h(64x64) ----
    float* Po = sh;               // reuse buffer 0
    float* Wo = sh + 2 * TILE_F;
#pragma unroll
    for (int r = 0; r < 4; r++) {
        float inv = 1.f / ssum[r];
        float4 o4 = {acc[r][0] * inv, acc[r][1] * inv, acc[r][2] * inv, acc[r][3] * inv};
        *(float4*)&Po[(ty * 4 + r) * 68 + tx * 4] = o4;
    }
#pragma unroll
    for (int l = 0; l < 4; l++) {
        int row = ty + l * 16;
        *(float4*)&Wo[row * 68 + tx * 4] = *(const float4*)&wo[(h * 64 + row) * 64 + tx * 4];
    }
    __syncthreads();

    float acc2[4][4];
#pragma unroll
    for (int r = 0; r < 4; r++)
#pragma unroll
        for (int c = 0; c < 4; c++) acc2[r][c] = 0.f;
#pragma unroll 8
    for (int k4 = 0; k4 < 64; k4 += 4) {
        float4 b0 = *(float4*)&Wo[(k4 + 0) * 68 + tx * 4];
        float4 b1 = *(float4*)&Wo[(k4 + 1) * 68 + tx * 4];
        float4 b2 = *(float4*)&Wo[(k4 + 2) * 68 + tx * 4];
        float4 b3 = *(float4*)&Wo[(k4 + 3) * 68 + tx * 4];
#pragma unroll
        for (int r = 0; r < 4; r++) {
            float4 a = *(float4*)&Po[(ty * 4 + r) * 68 + k4];
            acc2[r][0] += a.x * b0.x + a.y * b1.x + a.z * b2.x + a.w * b3.x;
            acc2[r][1] += a.x * b0.y + a.y * b1.y + a.z * b2.y + a.w * b3.y;
            acc2[r][2] += a.x * b0.z + a.y * b1.z + a.z * b2.z + a.w * b3.z;
            acc2[r][3] += a.x * b0.w + a.y * b1.w + a.z * b2.w + a.w * b3.w;
        }
    }
#pragma unroll
    for (int r = 0; r < 4; r++) {
        int t = i0 + ty * 4 + r;
        float4 o4 = {acc2[r][0], acc2[r][1], acc2[r][2], acc2[r][3]};
        *(float4*)&out[(b * TT + t) * DDIM + h * 64 + tx * 4] = o4;
    }
}

// ---------------------------------------------------------------------------
extern "C" void kernel_launch(void* const* d_in, const int* in_sizes, int n_in,
                              void* d_out, int out_size) {
    const float* x  = (const float*)d_in[0];
    const float* wq = (const float*)d_in[1];
    const float* wk = (const float*)d_in[2];
    const float* wv = (const float*)d_in[3];
    const float* wo = (const float*)d_in[4];
    float* out = (float*)d_out;

    const int PVSM_SMEM = 4 * TILE_F * 4;  // 69632 B
    cudaFuncSetAttribute(k_pvsm, cudaFuncAttributeMaxDynamicSharedMemorySize, PVSM_SMEM);

    k_qkv<<<dim3(4, 32, 3), 256>>>(x, wq, wk, wv);
    k_score<<<dim3(8, 8, 32), 256>>>();
    k_scan<<<256, 128>>>();
    k_pvsm<<<512, 256, PVSM_SMEM>>>(wo, out);
}